// round 4
// baseline (speedup 1.0000x reference)
#include <cuda_runtime.h>
#include <math.h>

#define NB 32
#define S  64
#define NP 16384   // 128*128 output points per batch

// Scratch (static __device__ — no allocation).
__device__ float2 g_G[NB * S * S];   // row-DFT intermediate
__device__ float2 g_F[NB * S * S];   // full 2D DFT, frequency-ordered (f = idx-32), pre-scaled 1/4096

// ---------------------------------------------------------------------------
// Stage 1a: G[b][k][c] = sum_a y[b][a][c] * exp(-2*pi*i*k*a/64)
// ---------------------------------------------------------------------------
__global__ __launch_bounds__(256) void dft_rows_kernel(const float* __restrict__ y)
{
    __shared__ float  sy[S * S];     // 16 KB
    __shared__ float2 tw[S];         // twiddles exp(-2*pi*i*j/64)

    const int b = blockIdx.x;
    const int t = threadIdx.x;

    const float* yb = y + b * S * S;
    for (int i = t; i < S * S; i += 256) sy[i] = yb[i];
    if (t < S) {
        float s, c;
        sincospif(-(float)t / 32.0f, &s, &c);   // -2*pi*t/64 = -pi*(t/32)
        tw[t] = make_float2(c, s);
    }
    __syncthreads();

    float2* Gb = g_G + b * S * S;
    for (int e = t; e < S * S; e += 256) {
        const int k = e >> 6;
        const int c = e & 63;
        float gr = 0.f, gi = 0.f;
#pragma unroll
        for (int a = 0; a < S; a++) {
            const float2 w = tw[(k * a) & 63];   // uniform across warp -> broadcast
            const float  v = sy[a * S + c];
            gr += v * w.x;
            gi += v * w.y;
        }
        Gb[e] = make_float2(gr, gi);
    }
}

// ---------------------------------------------------------------------------
// Stage 1b: F[b][k][m] = sum_c G[b][k][c] * exp(-2*pi*i*m*c/64)
// Stored permuted: Fp[k'][m'] = F[(k'+32)%64][(m'+32)%64], so freq = idx-32,
// and pre-scaled by 1/(S*S).
// ---------------------------------------------------------------------------
__global__ __launch_bounds__(256) void dft_cols_kernel()
{
    __shared__ float2 sG[S * S];     // 32 KB
    __shared__ float2 tw[S];

    const int b = blockIdx.x;
    const int t = threadIdx.x;

    const float2* Gb = g_G + b * S * S;
    for (int i = t; i < S * S; i += 256) sG[i] = Gb[i];
    if (t < S) {
        float s, c;
        sincospif(-(float)t / 32.0f, &s, &c);
        tw[t] = make_float2(c, s);
    }
    __syncthreads();

    float2* Fb = g_F + b * S * S;
    const float scale = 1.0f / (float)(S * S);
    for (int e = t; e < S * S; e += 256) {
        const int k = e >> 6;
        const int m = e & 63;
        float fr = 0.f, fi = 0.f;
#pragma unroll
        for (int c = 0; c < S; c++) {
            const float2 g = sG[k * S + c];       // uniform across warp -> broadcast
            const float2 w = tw[(m * c) & 63];
            fr += g.x * w.x - g.y * w.y;
            fi += g.x * w.y + g.y * w.x;
        }
        const int kp = (k + 32) & 63;
        const int mp = (m + 32) & 63;
        Fb[kp * S + mp] = make_float2(fr * scale, fi * scale);
    }
}

// ---------------------------------------------------------------------------
// Stage 2: per output point p with coords (x1,x2):
//   res = Re( sum_{k'} c1[k'] * sum_{m'} Fp[k'][m'] * c2[m'] )
// with c1[k'] = exp(2*pi*i*x1*(k'-32)), c2[m'] = exp(2*pi*i*x2*(m'-32)).
// c2 kept in registers using c2[64-m'] = conj(c2[m']) (33 complex values,
// c2[32] = 1). F broadcast from shared memory (identical across lanes).
// ---------------------------------------------------------------------------
__global__ __launch_bounds__(256) void interp_kernel(const float* __restrict__ xnew,
                                                     float* __restrict__ out)
{
    __shared__ float2 sF[S * S];     // 32 KB

    const int b = blockIdx.y;
    const int p = blockIdx.x * 256 + threadIdx.x;

    const float2* Fb = g_F + b * S * S;
    for (int i = threadIdx.x; i < S * S; i += 256) sF[i] = Fb[i];
    __syncthreads();

    const int base = (b * NP + p) * 2;
    const float x1 = xnew[base + 0];
    const float x2 = xnew[base + 1];

    // Unit-circle steps
    float w1r, w1i, w2r, w2i;
    sincospif(2.0f * x1, &w1i, &w1r);   // w1 = exp(+2*pi*i*x1)
    sincospif(2.0f * x2, &w2i, &w2r);   // w2 = exp(+2*pi*i*x2)

    // c1 start at freq -32: exp(-i*pi*(64*x1))
    float s1, cc1;
    sincospif(64.0f * x1, &s1, &cc1);
    float c1r = cc1, c1i = -s1;

    // c2[m'] for m'=0..32 (freq m'-32): c2[32]=1, step down by conj(w2)
    float c2r[33], c2i[33];
    c2r[32] = 1.0f; c2i[32] = 0.0f;
#pragma unroll
    for (int j = 32; j > 0; j--) {
        const float ar = c2r[j], ai = c2i[j];
        c2r[j - 1] = ar * w2r + ai * w2i;    // * conj(w2)
        c2i[j - 1] = ai * w2r - ar * w2i;
    }

    float res = 0.0f;
    const float2* Fk = sF;
#pragma unroll 1
    for (int k = 0; k < S; k++) {
        // 4 independent accumulation chains (pipeline the 4-cycle FFMA latency)
        float tr1 = 0.f, tr2 = 0.f, ti1 = 0.f, ti2 = 0.f;
#pragma unroll
        for (int m = 0; m < S; m++) {
            const float2 f = Fk[m];                       // LDS.64 broadcast
            const float cr = (m <= 32) ? c2r[m] :  c2r[64 - m];
            const float ci = (m <= 32) ? c2i[m] : -c2i[64 - m];
            tr1 += f.x * cr;
            tr2 += f.y * ci;
            ti1 += f.x * ci;
            ti2 += f.y * cr;
        }
        const float tr = tr1 - tr2;
        const float ti = ti1 + ti2;
        res += c1r * tr - c1i * ti;          // only the real part is needed

        // c1 *= w1
        const float nr = c1r * w1r - c1i * w1i;
        const float ni = c1r * w1i + c1i * w1r;
        c1r = nr; c1i = ni;

        Fk += S;
    }

    out[b * NP + p] = res;   // F pre-scaled by 1/4096
}

// ---------------------------------------------------------------------------
// Launch
// ---------------------------------------------------------------------------
extern "C" void kernel_launch(void* const* d_in, const int* in_sizes, int n_in,
                              void* d_out, int out_size)
{
    const float* y    = (const float*)d_in[0];   // [32, 64, 64]
    const float* xnew = (const float*)d_in[1];   // [32, 128, 128, 2]
    float*       out  = (float*)d_out;           // [32, 128, 128]

    dft_rows_kernel<<<NB, 256>>>(y);
    dft_cols_kernel<<<NB, 256>>>();

    dim3 grid(NP / 256, NB);                     // 64 x 32 blocks
    interp_kernel<<<grid, 256>>>(xnew, out);
}

// round 5
// speedup vs baseline: 1.5589x; 1.5589x over previous
#include <cuda_runtime.h>
#include <math.h>

#define NB 32
#define S  64
#define NP 16384   // 128*128 output points per batch

typedef unsigned long long ull;

// Scratch (static __device__ — no allocation).
__device__ float2 g_G[NB * S * S];    // row-DFT intermediate
__device__ float  g_Fr[NB * S * S];   // Re F, frequency-ordered (f = idx-32), scaled 1/4096
__device__ float  g_Fi[NB * S * S];   // Im F, same layout

// ---------------------------------------------------------------------------
// Packed f32x2 helpers (sm_103a FFMA2)
// ---------------------------------------------------------------------------
__device__ __forceinline__ ull pk(float lo, float hi) {
    ull r;
    asm("mov.b64 %0, {%1, %2};" : "=l"(r) : "f"(lo), "f"(hi));
    return r;
}
__device__ __forceinline__ void unpk(ull v, float& lo, float& hi) {
    asm("mov.b64 {%0, %1}, %2;" : "=f"(lo), "=f"(hi) : "l"(v));
}
#define FMA2(acc, a, b) asm("fma.rn.f32x2 %0, %1, %2, %0;" : "+l"(acc) : "l"(a), "l"(b))

// ---------------------------------------------------------------------------
// Stage 1a: G[b][k][c] = sum_a y[b][a][c] * exp(-2*pi*i*k*a/64)
// grid (NB, 4): each block does 1/4 of the 64x64 outputs.
// ---------------------------------------------------------------------------
__global__ __launch_bounds__(256) void dft_rows_kernel(const float* __restrict__ y)
{
    __shared__ float  sy[S * S];
    __shared__ float2 tw[S];

    const int b = blockIdx.x;
    const int t = threadIdx.x;

    const float* yb = y + b * S * S;
    for (int i = t; i < S * S; i += 256) sy[i] = yb[i];
    if (t < S) {
        float s, c;
        sincospif(-(float)t / 32.0f, &s, &c);
        tw[t] = make_float2(c, s);
    }
    __syncthreads();

    float2* Gb = g_G + b * S * S;
    int e = blockIdx.y * 1024 + t;
#pragma unroll 1
    for (int r = 0; r < 4; r++, e += 256) {
        const int k = e >> 6;
        const int c = e & 63;
        float gr = 0.f, gi = 0.f;
#pragma unroll
        for (int a = 0; a < S; a++) {
            const float2 w = tw[(k * a) & 63];
            const float  v = sy[a * S + c];
            gr += v * w.x;
            gi += v * w.y;
        }
        Gb[e] = make_float2(gr, gi);
    }
}

// ---------------------------------------------------------------------------
// Stage 1b: F[b][k][m] = sum_c G[b][k][c] * exp(-2*pi*i*m*c/64)
// Output permuted to frequency order (f = idx-32), SoA planes, scaled 1/4096.
// ---------------------------------------------------------------------------
__global__ __launch_bounds__(256) void dft_cols_kernel()
{
    __shared__ float2 sG[S * S];
    __shared__ float2 tw[S];

    const int b = blockIdx.x;
    const int t = threadIdx.x;

    const float2* Gb = g_G + b * S * S;
    for (int i = t; i < S * S; i += 256) sG[i] = Gb[i];
    if (t < S) {
        float s, c;
        sincospif(-(float)t / 32.0f, &s, &c);
        tw[t] = make_float2(c, s);
    }
    __syncthreads();

    const float scale = 1.0f / 4096.0f;
    int e = blockIdx.y * 1024 + t;
#pragma unroll 1
    for (int r = 0; r < 4; r++, e += 256) {
        const int k = e >> 6;
        const int m = e & 63;
        float fr = 0.f, fi = 0.f;
#pragma unroll
        for (int c = 0; c < S; c++) {
            const float2 g = sG[k * S + c];
            const float2 w = tw[(m * c) & 63];
            fr += g.x * w.x - g.y * w.y;
            fi += g.x * w.y + g.y * w.x;
        }
        const int kp = (k + 32) & 63;
        const int mp = (m + 32) & 63;
        const int o = b * S * S + kp * S + mp;
        g_Fr[o] = fr * scale;
        g_Fi[o] = fi * scale;
    }
}

// ---------------------------------------------------------------------------
// Stage 2: Hermitian-folded evaluation.
//   ynew = 2*sum_{k=1..31}(ca_k*A_k - sa_k*B_k) + (k=0 term) + (k=32 term)
//          - sin(64 pi x1)*sin(64 pi x2)*Fr[0][0]
// where A_k = sum_m Fr[k][m]*cb_m - Fi[k][m]*sb_m,
//       B_k = sum_m Fr[k][m]*sb_m + Fi[k][m]*cb_m,  with sb[0] forced to 0.
// Inner loop: packed FFMA2 over m-pairs; F rows broadcast via LDS.128.
// ---------------------------------------------------------------------------
__global__ __launch_bounds__(256, 1) void interp_kernel(const float* __restrict__ xnew,
                                                        float* __restrict__ out)
{
    __shared__ __align__(16) float sFr[33 * S];
    __shared__ __align__(16) float sFi[33 * S];

    const int b = blockIdx.y;
    const int p = blockIdx.x * 256 + threadIdx.x;

    const float* Fr = g_Fr + b * S * S;
    const float* Fi = g_Fi + b * S * S;
    for (int i = threadIdx.x; i < 33 * S; i += 256) {
        sFr[i] = Fr[i];
        sFi[i] = Fi[i];
    }
    __syncthreads();

    const int base = (b * NP + p) * 2;
    const float x1 = xnew[base + 0];
    const float x2 = xnew[base + 1];

    float w1r, w1i, w2r, w2i;
    sincospif(2.0f * x1, &w1i, &w1r);        // exp(+2 pi i x1)
    sincospif(2.0f * x2, &w2i, &w2r);        // exp(+2 pi i x2)
    float s1, c1v, s2, c2v;
    sincospif(64.0f * x1, &s1, &c1v);        // cos/sin(64 pi x1)
    sincospif(64.0f * x2, &s2, &c2v);        // cos/sin(64 pi x2)

    // Packed cb/sb pairs for m = 0..63 (freq m-32). Start at m=0:
    // cb = cos(-64 pi x2) = c2v, sb = sin(-64 pi x2) = -s2; stored sb[0] := 0.
    ull cbp[32], sbp[32];
    {
        float cr = c2v, si = -s2;
#pragma unroll
        for (int j = 0; j < 32; j++) {
            const float c0 = cr;
            const float s0 = (j == 0) ? 0.0f : si;
            float nr = cr * w2r - si * w2i;
            float ni = si * w2r + cr * w2i;
            cr = nr; si = ni;                 // now at m = 2j+1
            cbp[j] = pk(c0, cr);
            sbp[j] = pk(s0, si);
            nr = cr * w2r - si * w2i;
            ni = si * w2r + cr * w2i;
            cr = nr; si = ni;                 // now at m = 2j+2
        }
    }

    float res2 = 0.0f;   // all rows 0..32
    float res1 = 0.0f;   // edge rows (0 and 32) only
    float car = c1v;     // ca_0 = cos(-64 pi x1)
    float sai = -s1;     // sa_0 = sin(-64 pi x1)

#pragma unroll 1
    for (int k = 0; k < 33; k++) {
        const float* fr = &sFr[k * S];
        const float* fi = &sFi[k * S];
        ull aA = 0ull, aB = 0ull, bA = 0ull, bB = 0ull;
#pragma unroll
        for (int j = 0; j < 16; j++) {
            const ulonglong2 fp = *(const ulonglong2*)(fr + 4 * j);  // 4 Fr as 2 packed
            const ulonglong2 gp = *(const ulonglong2*)(fi + 4 * j);  // 4 Fi as 2 packed
            FMA2(aA, fp.x, cbp[2 * j]);
            FMA2(aB, gp.x, sbp[2 * j]);
            FMA2(bA, fp.x, sbp[2 * j]);
            FMA2(bB, gp.x, cbp[2 * j]);
            FMA2(aA, fp.y, cbp[2 * j + 1]);
            FMA2(aB, gp.y, sbp[2 * j + 1]);
            FMA2(bA, fp.y, sbp[2 * j + 1]);
            FMA2(bB, gp.y, cbp[2 * j + 1]);
        }
        float aA0, aA1, aB0, aB1, bA0, bA1, bB0, bB1;
        unpk(aA, aA0, aA1);
        unpk(aB, aB0, aB1);
        unpk(bA, bA0, bA1);
        unpk(bB, bB0, bB1);
        const float A = (aA0 + aA1) - (aB0 + aB1);
        const float B = (bA0 + bA1) + (bB0 + bB1);
        const float tterm = car * A - sai * B;
        res2 += tterm;
        res1 += (k == 0 || k == 32) ? tterm : 0.0f;

        // (ca,sa) *= exp(2 pi i x1)
        const float nr = car * w1r - sai * w1i;
        const float ni = sai * w1r + car * w1i;
        car = nr; sai = ni;
    }

    // total = 2*(pair rows) + edge rows + Nyquist-corner correction
    const float res = 2.0f * res2 - res1 - s1 * s2 * sFr[0];
    out[b * NP + p] = res;
}

// ---------------------------------------------------------------------------
// Launch
// ---------------------------------------------------------------------------
extern "C" void kernel_launch(void* const* d_in, const int* in_sizes, int n_in,
                              void* d_out, int out_size)
{
    const float* y    = (const float*)d_in[0];   // [32, 64, 64]
    const float* xnew = (const float*)d_in[1];   // [32, 128, 128, 2]
    float*       out  = (float*)d_out;           // [32, 128, 128]

    dft_rows_kernel<<<dim3(NB, 4), 256>>>(y);
    dft_cols_kernel<<<dim3(NB, 4), 256>>>();

    dim3 grid(NP / 256, NB);                     // 64 x 32 blocks
    interp_kernel<<<grid, 256>>>(xnew, out);
}

// round 6
// speedup vs baseline: 2.5376x; 1.6279x over previous
#include <cuda_runtime.h>
#include <math.h>

#define NB   32
#define S    64
#define NP   16384          // 128*128 output points per batch
#define RSTR 36             // folded-row stride in floats (33 data + 3 pad, 16B-aligned)
#define ASTR (33 * RSTR)    // per-array stride  = 1188 floats
#define FFSZ (4 * ASTR)     // per-batch folded block = 4752 floats (19008 B)

typedef unsigned long long ull;

// Scratch (static __device__ — no allocation).
__device__ float2 g_G[NB * S * S];                 // row-DFT intermediate
__device__ __align__(16) float g_FF[NB * FFSZ];    // folded F: [FrP, FiMn, FrM, FiP]

// ---------------------------------------------------------------------------
// Packed f32x2 helpers (sm_103a FFMA2)
// ---------------------------------------------------------------------------
__device__ __forceinline__ ull pk(float lo, float hi) {
    ull r;
    asm("mov.b64 %0, {%1, %2};" : "=l"(r) : "f"(lo), "f"(hi));
    return r;
}
__device__ __forceinline__ void unpk(ull v, float& lo, float& hi) {
    asm("mov.b64 {%0, %1}, %2;" : "=f"(lo), "=f"(hi) : "l"(v));
}
#define FMA2(acc, a, b) asm("fma.rn.f32x2 %0, %1, %2, %0;" : "+l"(acc) : "l"(a), "l"(b))

// ---------------------------------------------------------------------------
// Stage 1a: G[b][k][c] = sum_a y[b][a][c] * exp(-2*pi*i*k*a/64)
// ---------------------------------------------------------------------------
__global__ __launch_bounds__(256) void dft_rows_kernel(const float* __restrict__ y)
{
    __shared__ float  sy[S * S];
    __shared__ float2 tw[S];

    const int b = blockIdx.x;
    const int t = threadIdx.x;

    const float* yb = y + b * S * S;
    for (int i = t; i < S * S; i += 256) sy[i] = yb[i];
    if (t < S) {
        float s, c;
        sincospif(-(float)t / 32.0f, &s, &c);
        tw[t] = make_float2(c, s);
    }
    __syncthreads();

    float2* Gb = g_G + b * S * S;
    int e = blockIdx.y * 1024 + t;
#pragma unroll 1
    for (int r = 0; r < 4; r++, e += 256) {
        const int k = e >> 6;
        const int c = e & 63;
        float gr = 0.f, gi = 0.f;
#pragma unroll
        for (int a = 0; a < S; a++) {
            const float2 w = tw[(k * a) & 63];
            const float  v = sy[a * S + c];
            gr += v * w.x;
            gi += v * w.y;
        }
        Gb[e] = make_float2(gr, gi);
    }
}

// ---------------------------------------------------------------------------
// Stage 1b: column DFT producing FOLDED arrays directly.
// Frequency-ordered Fp[k'][m'] (freq = idx-32), rows k'=0..32 only (Hermitian
// k-fold), folded along m via coefficient parity (d = |m'-32| = 0..32):
//   FrP[d] = Fr[32+d]+Fr[32-d]   (d=0: Fr[m'=32]; d=32: Fr[m'=0])
//   FiP[d] = Fi[32+d]+Fi[32-d]
//   FrM[d] = Fr[32+d]-Fr[32-d]   (0 at d=0 and d=32 — Nyquist sb trick)
//   FiMn[d] = -(Fi[32+d]-Fi[32-d])  (0 at d=0 and d=32)
// Natural-order column for m'=32+d is d itself; for m'=32-d it's 64-d.
// Also stashes the corner F(-32,-32) at slot [FrP][k=0][34]. Scaled 1/4096.
// ---------------------------------------------------------------------------
__global__ __launch_bounds__(256) void dft_cols_fold_kernel()
{
    __shared__ float2 sG[S * S];
    __shared__ float2 tw[S];

    const int b = blockIdx.x;
    const int t = threadIdx.x;

    const float2* Gb = g_G + b * S * S;
    for (int i = t; i < S * S; i += 256) sG[i] = Gb[i];
    if (t < S) {
        float s, c;
        sincospif(-(float)t / 32.0f, &s, &c);
        tw[t] = make_float2(c, s);
    }
    float* FF = g_FF + b * FFSZ;
    // zero entire folded block (pads + edge FrM/FiMn slots stay 0)
    if (blockIdx.y == 0)
        for (int i = t; i < FFSZ; i += 256) FF[i] = 0.f;
    __syncthreads();

    const int e = blockIdx.y * 256 + t;
    if (e >= 33 * 33) return;
    // blockIdx.y==0 block zeroed; other blocks race-free because the zeroing
    // block also writes only its own e-range? NO — zeroing covers everything.
    // Ordering across blocks is provided by... see note below: zero pass is
    // done by y==0 block which ALSO computes e<256; other blocks may write
    // before zeroing lands. To avoid the race, non-zero slots are always
    // fully written by their owning compute thread, and zero-only slots
    // (pads, edge FrM/FiMn) are written ONLY by the y==0 block. Compute
    // threads below explicitly write 0 to their edge FrM/FiMn slots instead
    // of relying on the memset, so the memset only owns pad slots that no
    // compute thread touches. (Pad slots are read only after this kernel
    // completes — kernel boundary orders them.)
    const int k  = e / 33;
    const int d  = e - k * 33;
    const int kn = (k + 32) & 63;
    const int m1 = d;                 // natural col for m'=32+d (and d=0/32 edges)
    const int m2 = (64 - d) & 63;     // natural col for m'=32-d

    float fr1 = 0.f, fi1 = 0.f, fr2 = 0.f, fi2 = 0.f;
#pragma unroll
    for (int c = 0; c < S; c++) {
        const float2 g  = sG[kn * S + c];
        const float2 wa = tw[(m1 * c) & 63];
        const float2 wb = tw[(m2 * c) & 63];
        fr1 += g.x * wa.x - g.y * wa.y;
        fi1 += g.x * wa.y + g.y * wa.x;
        fr2 += g.x * wb.x - g.y * wb.y;
        fi2 += g.x * wb.y + g.y * wb.x;
    }
    const float scale = 1.0f / 4096.0f;
    fr1 *= scale; fi1 *= scale; fr2 *= scale; fi2 *= scale;

    const int  o    = k * RSTR + d;
    const bool edge = (d == 0) || (d == 32);
    FF[0 * ASTR + o] = edge ? fr1 : fr1 + fr2;    // FrP
    FF[3 * ASTR + o] = edge ? fi1 : fi1 + fi2;    // FiP
    FF[1 * ASTR + o] = edge ? 0.f : fi2 - fi1;    // FiMn
    FF[2 * ASTR + o] = edge ? 0.f : fr1 - fr2;    // FrM
    if (k == 0 && d == 32) FF[0 * ASTR + 34] = fr1;   // corner F(-32,-32)
}

// ---------------------------------------------------------------------------
// Stage 2: folded evaluation.
//   term_k = ca_k*A_k - sa_k*B_k
//   A_k = sum_d FrP*cb_d + FiMn*sb_d ;  B_k = sum_d FrM*sb_d + FiP*cb_d
//   ynew = sum_k w_k*term_k - s1*s2*F(-32,-32),  w_k = 1 (k=0,32) else 2
// cb_d = cos(2*pi*x2*d), sb_d = sin(2*pi*x2*d); ca starts at freq -32.
// All-packed FFMA2 inner loop; F rows broadcast via LDS.128.
// ---------------------------------------------------------------------------
__global__ __launch_bounds__(256, 2) void interp_kernel(const float* __restrict__ xnew,
                                                        float* __restrict__ out)
{
    __shared__ __align__(16) float sFF[FFSZ];    // 19008 B

    const int b = blockIdx.y;
    const int p = blockIdx.x * 256 + threadIdx.x;

    {
        const float4* src = (const float4*)(g_FF + b * FFSZ);
        float4*       dst = (float4*)sFF;
        for (int i = threadIdx.x; i < FFSZ / 4; i += 256) dst[i] = src[i];
    }
    __syncthreads();

    const int   base = (b * NP + p) * 2;
    const float x1 = xnew[base + 0];
    const float x2 = xnew[base + 1];

    float w1r, w1i, w2r, w2i, s1, c1v, s2, c2v;
    sincospif(2.0f * x1, &w1i, &w1r);
    sincospif(2.0f * x2, &w2i, &w2r);
    sincospif(64.0f * x1, &s1, &c1v);
    sincospif(64.0f * x2, &s2, &c2v);

    // packed cb/sb pairs along d = 0..33 (d=0: cos=1, sin=0 exact)
    ull cbp[17], sbp[17];
    {
        float cr = 1.0f, si = 0.0f;
#pragma unroll
        for (int j = 0; j < 17; j++) {
            const float c0 = cr, s0 = si;
            float nr = cr * w2r - si * w2i;
            float ni = si * w2r + cr * w2i;
            cr = nr; si = ni;
            cbp[j] = pk(c0, cr);
            sbp[j] = pk(s0, si);
            nr = cr * w2r - si * w2i;
            ni = si * w2r + cr * w2i;
            cr = nr; si = ni;
        }
    }

    ull   resp = 0ull;
    float car = c1v;      // cos(2*pi*x1*(-32))
    float sai = -s1;      // sin(2*pi*x1*(-32))

#pragma unroll 1
    for (int k = 0; k < 33; k++) {
        const float* rb = sFF + k * RSTR;
        const ulonglong2* pA = (const ulonglong2*)(rb);              // FrP
        const ulonglong2* pN = (const ulonglong2*)(rb + ASTR);       // FiMn
        const ulonglong2* pM = (const ulonglong2*)(rb + 2 * ASTR);   // FrM
        const ulonglong2* pP = (const ulonglong2*)(rb + 3 * ASTR);   // FiP

        ull A1 = 0ull, A2 = 0ull, B1 = 0ull, B2 = 0ull;
#pragma unroll
        for (int j = 0; j < 8; j++) {
            const ulonglong2 a = pA[j];
            const ulonglong2 n = pN[j];
            const ulonglong2 m = pM[j];
            const ulonglong2 q = pP[j];
            FMA2(A1, a.x, cbp[2 * j]);     FMA2(A2, n.x, sbp[2 * j]);
            FMA2(B1, m.x, sbp[2 * j]);     FMA2(B2, q.x, cbp[2 * j]);
            FMA2(A1, a.y, cbp[2 * j + 1]); FMA2(A2, n.y, sbp[2 * j + 1]);
            FMA2(B1, m.y, sbp[2 * j + 1]); FMA2(B2, q.y, cbp[2 * j + 1]);
        }
        {   // tail: d = 32 (pad d = 33 is zero)
            const ull a = *(const ull*)(rb + 32);
            const ull n = *(const ull*)(rb + ASTR + 32);
            const ull m = *(const ull*)(rb + 2 * ASTR + 32);
            const ull q = *(const ull*)(rb + 3 * ASTR + 32);
            FMA2(A1, a, cbp[16]);  FMA2(A2, n, sbp[16]);
            FMA2(B1, m, sbp[16]);  FMA2(B2, q, cbp[16]);
        }

        const float w   = (k == 0 || k == 32) ? 1.0f : 2.0f;
        const float wc  = w * car;
        const float wns = -w * sai;
        const ull wcp  = pk(wc, wc);
        const ull wnsp = pk(wns, wns);
        FMA2(resp, wcp, A1);
        FMA2(resp, wcp, A2);
        FMA2(resp, wnsp, B1);
        FMA2(resp, wnsp, B2);

        const float nr = car * w1r - sai * w1i;
        const float ni = sai * w1r + car * w1i;
        car = nr; sai = ni;
    }

    float rlo, rhi;
    unpk(resp, rlo, rhi);
    out[b * NP + p] = rlo + rhi - s1 * s2 * sFF[34];
}

// ---------------------------------------------------------------------------
// Launch
// ---------------------------------------------------------------------------
extern "C" void kernel_launch(void* const* d_in, const int* in_sizes, int n_in,
                              void* d_out, int out_size)
{
    const float* y    = (const float*)d_in[0];   // [32, 64, 64]
    const float* xnew = (const float*)d_in[1];   // [32, 128, 128, 2]
    float*       out  = (float*)d_out;           // [32, 128, 128]

    dft_rows_kernel<<<dim3(NB, 4), 256>>>(y);
    dft_cols_fold_kernel<<<dim3(NB, 5), 256>>>();   // 5*256 >= 33*33

    dim3 grid(NP / 256, NB);
    interp_kernel<<<grid, 256>>>(xnew, out);
}

// round 16
// speedup vs baseline: 3.6919x; 1.4549x over previous
#include <cuda_runtime.h>
#include <math.h>

#define NB 32
#define S  64
#define NP 16384        // 128*128 output points per batch
#define NF 128          // fine (oversampled) grid, sigma = 2
#define BETA 18.4f      // ES kernel beta = 2.30 * w, w = 8, alpha = 4

// Scratch (static __device__ — no allocation).
__device__ float2 g_G[NB * S * S];        // row-DFT intermediate
__device__ float  g_ipsi[36];             // 1/psi_hat(|f|), f = 0..32
__device__ float2 g_H[NB * S * S];        // deconvolved spectrum, ALL 64 rows
__device__ float2 g_T[NB * S * NF];       // column-transformed to fine grid
__device__ float  g_fine[NB * NF * NF];   // real fine grid

// ---------------------------------------------------------------------------
// psi_hat(f) = 2 * int_0^4 exp(beta*(sqrt(1-(z/4)^2)-1)) * cos(pi f z / 64) dz
// Midpoint rule, 2048 points, 8 threads per f (f = 0..32).
// ---------------------------------------------------------------------------
__global__ void psihat_kernel()
{
    const int t = threadIdx.x;
    const int f = t >> 3;
    const int r = t & 7;

    const float h = 4.0f / 2048.0f;
    float sum = 0.0f;
    for (int i = r * 256; i < r * 256 + 256; i++) {
        const float z = ((float)i + 0.5f) * h;
        const float tt = fmaxf(1.0f - z * z * (1.0f / 16.0f), 0.0f);
        const float psi = expf(BETA * (sqrtf(tt) - 1.0f));
        sum += psi * cospif((float)f * z * (1.0f / 64.0f));
    }
    sum += __shfl_down_sync(0xffffffffu, sum, 4, 8);
    sum += __shfl_down_sync(0xffffffffu, sum, 2, 8);
    sum += __shfl_down_sync(0xffffffffu, sum, 1, 8);
    if (r == 0 && f < 33) g_ipsi[f] = 1.0f / (2.0f * h * sum);
}

// ---------------------------------------------------------------------------
// Stage 1a: G[b][k][c] = sum_a y[b][a][c] * exp(-2*pi*i*k*a/64)
// ---------------------------------------------------------------------------
__global__ __launch_bounds__(256) void dft_rows_kernel(const float* __restrict__ y)
{
    __shared__ float  sy[S * S];
    __shared__ float2 tw[S];

    const int b = blockIdx.x;
    const int t = threadIdx.x;

    const float* yb = y + b * S * S;
    for (int i = t; i < S * S; i += 256) sy[i] = yb[i];
    if (t < S) {
        float s, c;
        sincospif(-(float)t / 32.0f, &s, &c);
        tw[t] = make_float2(c, s);
    }
    __syncthreads();

    float2* Gb = g_G + b * S * S;
    int e = blockIdx.y * 1024 + t;
#pragma unroll 1
    for (int rr = 0; rr < 4; rr++, e += 256) {
        const int k = e >> 6;
        const int c = e & 63;
        float gr = 0.f, gi = 0.f;
#pragma unroll
        for (int a = 0; a < S; a++) {
            const float2 w = tw[(k * a) & 63];
            const float  v = sy[a * S + c];
            gr += v * w.x;
            gi += v * w.y;
        }
        Gb[e] = make_float2(gr, gi);
    }
}

// ---------------------------------------------------------------------------
// Stage 1b: H[k][m] = (col-DFT of G)[k][m] * ipsi(|fk|) * ipsi(|fm|) / 4096
// ALL 64 rows, natural FFT ordering. |f| = idx<=32 ? idx : 64-idx.
// ---------------------------------------------------------------------------
__global__ __launch_bounds__(256) void dft_cols_deconv_kernel()
{
    __shared__ float2 sG[S * S];
    __shared__ float2 tw[S];
    __shared__ float  sip[33];

    const int b = blockIdx.x;
    const int t = threadIdx.x;

    const float2* Gb = g_G + b * S * S;
    for (int i = t; i < S * S; i += 256) sG[i] = Gb[i];
    if (t < S) {
        float s, c;
        sincospif(-(float)t / 32.0f, &s, &c);
        tw[t] = make_float2(c, s);
    }
    if (t < 33) sip[t] = g_ipsi[t];
    __syncthreads();

    const int e = blockIdx.y * 256 + t;   // 16 blocks * 256 = 4096 = 64*64
    const int k = e >> 6;
    const int m = e & 63;

    float fr = 0.f, fi = 0.f;
#pragma unroll
    for (int c = 0; c < S; c++) {
        const float2 g = sG[k * S + c];
        const float2 w = tw[(m * c) & 63];
        fr += g.x * w.x - g.y * w.y;
        fi += g.x * w.y + g.y * w.x;
    }
    const int ak = (k <= 32) ? k : (64 - k);
    const int am = (m <= 32) ? m : (64 - m);
    const float sc = (1.0f / 4096.0f) * sip[ak] * sip[am];
    g_H[(b * S + k) * S + m] = make_float2(fr * sc, fi * sc);
}

// ---------------------------------------------------------------------------
// Stage 2a: T[b][k][n2] = sum_m H[k][m] * exp(+2*pi*i * n2 * fm / 128)
// fm = m (m<32), m-64 (m>=32). Exact: the m>=32 half carries factor (-1)^n2.
// ---------------------------------------------------------------------------
__global__ __launch_bounds__(128) void fine_cols_kernel()
{
    const int b  = blockIdx.x;
    const int k  = blockIdx.y;       // 0..63
    const int n2 = threadIdx.x;

    const float2* __restrict__ Hr = g_H + (b * S + k) * S;

    float sp, cp;
    sincospif((float)n2 / 64.0f, &sp, &cp);   // step exp(2*pi*i*n2/128)

    float pr = 1.f, pi_ = 0.f;
    float Ar = 0.f, Ai = 0.f, Br = 0.f, Bi = 0.f;
#pragma unroll
    for (int m = 0; m < 32; m++) {
        const float2 hv = Hr[m];
        Ar += hv.x * pr - hv.y * pi_;
        Ai += hv.x * pi_ + hv.y * pr;
        const float nr = pr * cp - pi_ * sp;
        const float ni = pi_ * cp + pr * sp;
        pr = nr; pi_ = ni;
    }
#pragma unroll
    for (int m = 32; m < 64; m++) {
        const float2 hv = Hr[m];
        Br += hv.x * pr - hv.y * pi_;
        Bi += hv.x * pi_ + hv.y * pr;
        const float nr = pr * cp - pi_ * sp;
        const float ni = pi_ * cp + pr * sp;
        pr = nr; pi_ = ni;
    }
    const float sgn = (n2 & 1) ? -1.0f : 1.0f;
    g_T[(b * S + k) * NF + n2] = make_float2(Ar + sgn * Br, Ai + sgn * Bi);
}

// ---------------------------------------------------------------------------
// Stage 2b: fine[n1][n2] = Re sum_{k=0..63} T[k][n2] exp(2*pi*i * n1 * fk/128)
// fk = k (k<32), k-64 (k>=32): k>=32 half carries factor (-1)^n1. Exact.
// ---------------------------------------------------------------------------
__global__ __launch_bounds__(128) void fine_rows_kernel()
{
    const int b  = blockIdx.x;
    const int n1 = blockIdx.y;
    const int n2 = threadIdx.x;

    const float2* __restrict__ Tb = g_T + b * S * NF + n2;

    float sp, cp;
    sincospif((float)n1 / 64.0f, &sp, &cp);   // step exp(2*pi*i*n1/128)

    float pr = 1.f, pi_ = 0.f;
    float Ar = 0.f, Br = 0.f;
#pragma unroll
    for (int k = 0; k < 32; k++) {
        const float2 tk = Tb[k * NF];
        Ar += tk.x * pr - tk.y * pi_;
        const float nr = pr * cp - pi_ * sp;
        const float ni = pi_ * cp + pr * sp;
        pr = nr; pi_ = ni;
    }
#pragma unroll
    for (int k = 32; k < 64; k++) {
        const float2 tk = Tb[k * NF];
        Br += tk.x * pr - tk.y * pi_;
        const float nr = pr * cp - pi_ * sp;
        const float ni = pi_ * cp + pr * sp;
        pr = nr; pi_ = ni;
    }
    const float sgn = (n1 & 1) ? -1.0f : 1.0f;
    g_fine[b * NF * NF + n1 * NF + n2] = Ar + sgn * Br;
}

// ---------------------------------------------------------------------------
// Stage 3: ES interpolation off the fine grid held in SHARED memory.
// 8 exact row taps; 12 column taps (zero-clamped ES weights) so each row is
// 3 aligned LDS.128 — float4-granular wrap is exact since base % 4 == 0.
// One block = 1/8 of a batch's points; dynamic smem = 64 KB (2 blocks/SM).
// ---------------------------------------------------------------------------
__global__ __launch_bounds__(256) void interp_spread_kernel(const float* __restrict__ xnew,
                                                            float* __restrict__ out)
{
    extern __shared__ __align__(16) float sg[];   // NF*NF = 64 KB

    const int b = blockIdx.y;

    {
        const float4* src = (const float4*)(g_fine + b * NF * NF);
        float4*       dst = (float4*)sg;
        for (int i = threadIdx.x; i < NF * NF / 4; i += 256) dst[i] = src[i];
    }
    __syncthreads();

    const float2* xb = (const float2*)xnew + b * NP + blockIdx.x * 2048;
    float*        ob = out + b * NP + blockIdx.x * 2048;

#pragma unroll 1
    for (int it = 0; it < 8; it++) {
        const int   pp = it * 256 + threadIdx.x;
        const float2 xv = xb[pp];

        const float u  = xv.x * 128.0f;
        const float v  = xv.y * 128.0f;
        const float iu = floorf(u);
        const float fu = u - iu;
        const int   r0 = (int)iu - 3;
        const int   iv = (int)floorf(v);
        const int   c0 = iv - 3;
        const int   bc = c0 & ~3;            // aligned base (can be -4)
        const float zc = v - (float)bc;      // in [3, 7)

        // 12 column weights, zero outside |z| < 4
        float wc[12];
#pragma unroll
        for (int j = 0; j < 12; j++) {
            const float z = zc - (float)j;
            const float tt = 1.0f - z * z * (1.0f / 16.0f);
            wc[j] = (tt > 0.0f) ? __expf(BETA * (sqrtf(tt) - 1.0f)) : 0.0f;
        }
        // 8 row weights (always in support)
        float wr[8];
#pragma unroll
        for (int i = 0; i < 8; i++) {
            const float z = fu + (float)(3 - i);
            const float tt = fmaxf(1.0f - z * z * (1.0f / 16.0f), 0.0f);
            wr[i] = __expf(BETA * (sqrtf(tt) - 1.0f));
        }

        const int cA = bc & 127;
        const int cB = (bc + 4) & 127;
        const int cC = (bc + 8) & 127;

        float acc = 0.0f;
#pragma unroll
        for (int i = 0; i < 8; i++) {
            const float* row = sg + ((r0 + i) & 127) * NF;
            const float4 qa = *(const float4*)(row + cA);
            const float4 qb = *(const float4*)(row + cB);
            const float4 qc = *(const float4*)(row + cC);
            float rs;
            rs  = wc[0] * qa.x + wc[1]  * qa.y + wc[2]  * qa.z + wc[3]  * qa.w;
            rs += wc[4] * qb.x + wc[5]  * qb.y + wc[6]  * qb.z + wc[7]  * qb.w;
            rs += wc[8] * qc.x + wc[9]  * qc.y + wc[10] * qc.z + wc[11] * qc.w;
            acc += wr[i] * rs;
        }
        ob[pp] = acc;
    }
}

// ---------------------------------------------------------------------------
// Launch
// ---------------------------------------------------------------------------
extern "C" void kernel_launch(void* const* d_in, const int* in_sizes, int n_in,
                              void* d_out, int out_size)
{
    const float* y    = (const float*)d_in[0];   // [32, 64, 64]
    const float* xnew = (const float*)d_in[1];   // [32, 128, 128, 2]
    float*       out  = (float*)d_out;           // [32, 128, 128]

    static int smem_set = 0;
    if (!smem_set) {
        cudaFuncSetAttribute(interp_spread_kernel,
                             cudaFuncAttributeMaxDynamicSharedMemorySize,
                             NF * NF * (int)sizeof(float));
        smem_set = 1;
    }

    psihat_kernel<<<1, 288>>>();
    dft_rows_kernel<<<dim3(NB, 4), 256>>>(y);
    dft_cols_deconv_kernel<<<dim3(NB, 16), 256>>>();
    fine_cols_kernel<<<dim3(NB, S), 128>>>();
    fine_rows_kernel<<<dim3(NB, NF), 128>>>();
    interp_spread_kernel<<<dim3(8, NB), 256, NF * NF * sizeof(float)>>>(xnew, out);
}

// round 17
// speedup vs baseline: 3.7173x; 1.0069x over previous
#include <cuda_runtime.h>
#include <math.h>

#define NB 32
#define S  64
#define NP 16384        // 128*128 output points per batch
#define NF 128          // fine (oversampled) grid, sigma = 2
#define BETA 18.4f      // ES kernel beta = 2.30 * w, w = 8, alpha = 4

// Scratch (static __device__ — no allocation).
__device__ float2 g_G[NB * S * S];        // row-DFT intermediate
__device__ float  g_ipsi[36];             // 1/psi_hat(|f|), f = 0..32
__device__ float2 g_H[NB * S * S];        // deconvolved spectrum, ALL 64 rows
__device__ float2 g_T[NB * S * NF];       // column-transformed to fine grid
__device__ float  g_fine[NB * NF * NF];   // real fine grid

// ---------------------------------------------------------------------------
// psi_hat(f) = 2 * int_0^4 exp(beta*(sqrt(1-(z/4)^2)-1)) * cos(pi f z / 64) dz
// Midpoint rule, 2048 points, 8 threads per f (f = 0..32).
// ---------------------------------------------------------------------------
__global__ void psihat_kernel()
{
    const int t = threadIdx.x;
    const int f = t >> 3;
    const int r = t & 7;

    const float h = 4.0f / 2048.0f;
    float sum = 0.0f;
    for (int i = r * 256; i < r * 256 + 256; i++) {
        const float z = ((float)i + 0.5f) * h;
        const float tt = fmaxf(1.0f - z * z * (1.0f / 16.0f), 0.0f);
        const float psi = expf(BETA * (sqrtf(tt) - 1.0f));
        sum += psi * cospif((float)f * z * (1.0f / 64.0f));
    }
    sum += __shfl_down_sync(0xffffffffu, sum, 4, 8);
    sum += __shfl_down_sync(0xffffffffu, sum, 2, 8);
    sum += __shfl_down_sync(0xffffffffu, sum, 1, 8);
    if (r == 0 && f < 33) g_ipsi[f] = 1.0f / (2.0f * h * sum);
}

// ---------------------------------------------------------------------------
// Stage 1a: G[b][k][c] = sum_a y[b][a][c] * exp(-2*pi*i*k*a/64)
// ---------------------------------------------------------------------------
__global__ __launch_bounds__(256) void dft_rows_kernel(const float* __restrict__ y)
{
    __shared__ float  sy[S * S];
    __shared__ float2 tw[S];

    const int b = blockIdx.x;
    const int t = threadIdx.x;

    const float* yb = y + b * S * S;
    for (int i = t; i < S * S; i += 256) sy[i] = yb[i];
    if (t < S) {
        float s, c;
        sincospif(-(float)t / 32.0f, &s, &c);
        tw[t] = make_float2(c, s);
    }
    __syncthreads();

    float2* Gb = g_G + b * S * S;
    int e = blockIdx.y * 1024 + t;
#pragma unroll 1
    for (int rr = 0; rr < 4; rr++, e += 256) {
        const int k = e >> 6;
        const int c = e & 63;
        float gr = 0.f, gi = 0.f;
#pragma unroll
        for (int a = 0; a < S; a++) {
            const float2 w = tw[(k * a) & 63];
            const float  v = sy[a * S + c];
            gr += v * w.x;
            gi += v * w.y;
        }
        Gb[e] = make_float2(gr, gi);
    }
}

// ---------------------------------------------------------------------------
// Stage 1b: H[k][m] = (col-DFT of G)[k][m] * ipsi(|fk|) * ipsi(|fm|) / 4096
// ALL 64 rows, natural FFT ordering. |f| = idx<=32 ? idx : 64-idx.
// ---------------------------------------------------------------------------
__global__ __launch_bounds__(256) void dft_cols_deconv_kernel()
{
    __shared__ float2 sG[S * S];
    __shared__ float2 tw[S];
    __shared__ float  sip[33];

    const int b = blockIdx.x;
    const int t = threadIdx.x;

    const float2* Gb = g_G + b * S * S;
    for (int i = t; i < S * S; i += 256) sG[i] = Gb[i];
    if (t < S) {
        float s, c;
        sincospif(-(float)t / 32.0f, &s, &c);
        tw[t] = make_float2(c, s);
    }
    if (t < 33) sip[t] = g_ipsi[t];
    __syncthreads();

    const int e = blockIdx.y * 256 + t;   // 16 blocks * 256 = 4096 = 64*64
    const int k = e >> 6;
    const int m = e & 63;

    float fr = 0.f, fi = 0.f;
#pragma unroll
    for (int c = 0; c < S; c++) {
        const float2 g = sG[k * S + c];
        const float2 w = tw[(m * c) & 63];
        fr += g.x * w.x - g.y * w.y;
        fi += g.x * w.y + g.y * w.x;
    }
    const int ak = (k <= 32) ? k : (64 - k);
    const int am = (m <= 32) ? m : (64 - m);
    const float sc = (1.0f / 4096.0f) * sip[ak] * sip[am];
    g_H[(b * S + k) * S + m] = make_float2(fr * sc, fi * sc);
}

// ---------------------------------------------------------------------------
// Stage 2a: T[b][k][n2] = sum_m H[k][m] * exp(+2*pi*i * n2 * fm / 128)
// fm = m (m<32), m-64 (m>=32). Exact: the m>=32 half carries factor (-1)^n2.
// ---------------------------------------------------------------------------
__global__ __launch_bounds__(128) void fine_cols_kernel()
{
    const int b  = blockIdx.x;
    const int k  = blockIdx.y;       // 0..63
    const int n2 = threadIdx.x;

    const float2* __restrict__ Hr = g_H + (b * S + k) * S;

    float sp, cp;
    sincospif((float)n2 / 64.0f, &sp, &cp);   // step exp(2*pi*i*n2/128)

    float pr = 1.f, pi_ = 0.f;
    float Ar = 0.f, Ai = 0.f, Br = 0.f, Bi = 0.f;
#pragma unroll
    for (int m = 0; m < 32; m++) {
        const float2 hv = Hr[m];
        Ar += hv.x * pr - hv.y * pi_;
        Ai += hv.x * pi_ + hv.y * pr;
        const float nr = pr * cp - pi_ * sp;
        const float ni = pi_ * cp + pr * sp;
        pr = nr; pi_ = ni;
    }
#pragma unroll
    for (int m = 32; m < 64; m++) {
        const float2 hv = Hr[m];
        Br += hv.x * pr - hv.y * pi_;
        Bi += hv.x * pi_ + hv.y * pr;
        const float nr = pr * cp - pi_ * sp;
        const float ni = pi_ * cp + pr * sp;
        pr = nr; pi_ = ni;
    }
    const float sgn = (n2 & 1) ? -1.0f : 1.0f;
    g_T[(b * S + k) * NF + n2] = make_float2(Ar + sgn * Br, Ai + sgn * Bi);
}

// ---------------------------------------------------------------------------
// Stage 2b: fine[n1][n2] = Re sum_{k=0..63} T[k][n2] exp(2*pi*i * n1 * fk/128)
// fk = k (k<32), k-64 (k>=32): k>=32 half carries factor (-1)^n1. Exact.
// ---------------------------------------------------------------------------
__global__ __launch_bounds__(128) void fine_rows_kernel()
{
    const int b  = blockIdx.x;
    const int n1 = blockIdx.y;
    const int n2 = threadIdx.x;

    const float2* __restrict__ Tb = g_T + b * S * NF + n2;

    float sp, cp;
    sincospif((float)n1 / 64.0f, &sp, &cp);   // step exp(2*pi*i*n1/128)

    float pr = 1.f, pi_ = 0.f;
    float Ar = 0.f, Br = 0.f;
#pragma unroll
    for (int k = 0; k < 32; k++) {
        const float2 tk = Tb[k * NF];
        Ar += tk.x * pr - tk.y * pi_;
        const float nr = pr * cp - pi_ * sp;
        const float ni = pi_ * cp + pr * sp;
        pr = nr; pi_ = ni;
    }
#pragma unroll
    for (int k = 32; k < 64; k++) {
        const float2 tk = Tb[k * NF];
        Br += tk.x * pr - tk.y * pi_;
        const float nr = pr * cp - pi_ * sp;
        const float ni = pi_ * cp + pr * sp;
        pr = nr; pi_ = ni;
    }
    const float sgn = (n1 & 1) ? -1.0f : 1.0f;
    g_fine[b * NF * NF + n1 * NF + n2] = Ar + sgn * Br;
}

// ---------------------------------------------------------------------------
// Stage 3: ES interpolation off the fine grid held in SHARED memory.
// 8 exact row taps; 12 column taps (zero-clamped ES weights) so each row is
// 3 aligned LDS.128 — float4-granular wrap is exact since base % 4 == 0.
// One block = 1/8 of a batch's points; dynamic smem = 64 KB (2 blocks/SM).
// ---------------------------------------------------------------------------
__global__ __launch_bounds__(256) void interp_spread_kernel(const float* __restrict__ xnew,
                                                            float* __restrict__ out)
{
    extern __shared__ __align__(16) float sg[];   // NF*NF = 64 KB

    const int b = blockIdx.y;

    {
        const float4* src = (const float4*)(g_fine + b * NF * NF);
        float4*       dst = (float4*)sg;
        for (int i = threadIdx.x; i < NF * NF / 4; i += 256) dst[i] = src[i];
    }
    __syncthreads();

    const float2* xb = (const float2*)xnew + b * NP + blockIdx.x * 2048;
    float*        ob = out + b * NP + blockIdx.x * 2048;

#pragma unroll 1
    for (int it = 0; it < 8; it++) {
        const int   pp = it * 256 + threadIdx.x;
        const float2 xv = xb[pp];

        const float u  = xv.x * 128.0f;
        const float v  = xv.y * 128.0f;
        const float iu = floorf(u);
        const float fu = u - iu;
        const int   r0 = (int)iu - 3;
        const int   iv = (int)floorf(v);
        const int   c0 = iv - 3;
        const int   bc = c0 & ~3;            // aligned base (can be -4)
        const float zc = v - (float)bc;      // in [3, 7)

        // 12 column weights, zero outside |z| < 4
        float wc[12];
#pragma unroll
        for (int j = 0; j < 12; j++) {
            const float z = zc - (float)j;
            const float tt = 1.0f - z * z * (1.0f / 16.0f);
            wc[j] = (tt > 0.0f) ? __expf(BETA * (sqrtf(tt) - 1.0f)) : 0.0f;
        }
        // 8 row weights (always in support)
        float wr[8];
#pragma unroll
        for (int i = 0; i < 8; i++) {
            const float z = fu + (float)(3 - i);
            const float tt = fmaxf(1.0f - z * z * (1.0f / 16.0f), 0.0f);
            wr[i] = __expf(BETA * (sqrtf(tt) - 1.0f));
        }

        const int cA = bc & 127;
        const int cB = (bc + 4) & 127;
        const int cC = (bc + 8) & 127;

        float acc = 0.0f;
#pragma unroll
        for (int i = 0; i < 8; i++) {
            const float* row = sg + ((r0 + i) & 127) * NF;
            const float4 qa = *(const float4*)(row + cA);
            const float4 qb = *(const float4*)(row + cB);
            const float4 qc = *(const float4*)(row + cC);
            float rs;
            rs  = wc[0] * qa.x + wc[1]  * qa.y + wc[2]  * qa.z + wc[3]  * qa.w;
            rs += wc[4] * qb.x + wc[5]  * qb.y + wc[6]  * qb.z + wc[7]  * qb.w;
            rs += wc[8] * qc.x + wc[9]  * qc.y + wc[10] * qc.z + wc[11] * qc.w;
            acc += wr[i] * rs;
        }
        ob[pp] = acc;
    }
}

// ---------------------------------------------------------------------------
// Launch
// ---------------------------------------------------------------------------
extern "C" void kernel_launch(void* const* d_in, const int* in_sizes, int n_in,
                              void* d_out, int out_size)
{
    const float* y    = (const float*)d_in[0];   // [32, 64, 64]
    const float* xnew = (const float*)d_in[1];   // [32, 128, 128, 2]
    float*       out  = (float*)d_out;           // [32, 128, 128]

    static int smem_set = 0;
    if (!smem_set) {
        cudaFuncSetAttribute(interp_spread_kernel,
                             cudaFuncAttributeMaxDynamicSharedMemorySize,
                             NF * NF * (int)sizeof(float));
        smem_set = 1;
    }

    psihat_kernel<<<1, 288>>>();
    dft_rows_kernel<<<dim3(NB, 4), 256>>>(y);
    dft_cols_deconv_kernel<<<dim3(NB, 16), 256>>>();
    fine_cols_kernel<<<dim3(NB, S), 128>>>();
    fine_rows_kernel<<<dim3(NB, NF), 128>>>();
    interp_spread_kernel<<<dim3(8, NB), 256, NF * NF * sizeof(float)>>>(xnew, out);
}